// round 1
// baseline (speedup 1.0000x reference)
#include <cuda_runtime.h>
#include <math.h>

// Problem constants (fixed by the reference setup)
#define NFRAG     131072
#define NCELLS    200
#define NGENES_MB 500
#define NSEG      (NCELLS * NGENES_MB)   // 100000
#define NFREQ     50
#define ENC       200                    // 4 * NFREQ
#define EDIM      10
#define ROWP      12                     // padded row stride (floats) for float4 LDS
#define MAXF      2048                   // max fragments per gene slot (mean ~262)

// Scratch (no cudaMalloc allowed)
__device__ int   g_seg_start[NSEG + 1];
__device__ float g_freqs[NFREQ];

// ---------------------------------------------------------------------------
// Kernel 1: exact f32 frequencies via double pow (matches jnp f32 freqs ~1ulp)
// ---------------------------------------------------------------------------
__global__ void init_freqs_kernel() {
    int j = threadIdx.x;
    if (j < NFREQ) {
        double e = (2.0 * (double)(j + 1)) / (double)NFREQ;
        g_freqs[j] = (float)(1.0 / pow(1000.0, e));
    }
}

// ---------------------------------------------------------------------------
// Kernel 2: segment boundaries by binary search over sorted cellxgene index
// ---------------------------------------------------------------------------
__global__ void seg_bounds_kernel(const int* __restrict__ ix) {
    int s = blockIdx.x * blockDim.x + threadIdx.x;
    if (s > NSEG) return;
    int lo = 0, hi = NFRAG;
    while (lo < hi) {
        int mid = (lo + hi) >> 1;
        if (ix[mid] < s) lo = mid + 1; else hi = mid;
    }
    g_seg_start[s] = lo;
}

// ---------------------------------------------------------------------------
// FMA-pipe sincos: Cody-Waite pi/2 reduction + Cephes minimax polys.
// Accurate to ~1e-7 abs for |x| <= ~2^23 * pi/2 (we only see |x| < ~4000).
// ---------------------------------------------------------------------------
__device__ __forceinline__ void sincos_fast(float x, float& sv, float& cv) {
    float q = rintf(x * 0.63661977236758134f);        // 2/pi
    int   k = (int)q;                                  // exact (q is integral)
    float r = fmaf(q, -1.57079637050628662109375f, x); // pi/2 hi
    r = fmaf(q, 4.37113900018624283e-8f, r);           // pi/2 lo correction
    float s2 = r * r;
    // sin(r)
    float ps = fmaf(-1.9515295891e-4f, s2, 8.3321608736e-3f);
    ps = fmaf(ps, s2, -1.6666654611e-1f);
    float sr = fmaf(ps, s2 * r, r);
    // cos(r)
    float pc = fmaf(2.443315711809948e-5f, s2, -1.388731625493765e-3f);
    pc = fmaf(pc, s2, 4.166664568298827e-2f);
    pc = fmaf(pc, s2, -0.5f);
    float cr = fmaf(pc, s2, 1.0f);
    // quadrant (bitwise works for negative k too)
    float ss = (k & 1) ? cr : sr;
    float cc = (k & 1) ? sr : cr;
    if (k & 2)        ss = -ss;
    if ((k + 1) & 2)  cc = -cc;
    sv = ss; cv = cc;
}

// ---------------------------------------------------------------------------
// Kernel 3: one block per gene slot g.
//   - stage W1[genes_oi[g]] (200x10, padded to 200x12) in SMEM (broadcast reads)
//   - gather the slot's fragments (segments g, g+500, ...) via block scan
//   - per fragment: sine-encode + 200x10 dot + sigmoid + w2-reduce -> svals
//   - per-cell ordered reduction -> out[c, g]  (fully deterministic, no atomics)
// ---------------------------------------------------------------------------
__global__ __launch_bounds__(256) void frag_gene_kernel(
    const float2* __restrict__ coords,
    const int*    __restrict__ genes_oi,
    const float*  __restrict__ W1,
    const float*  __restrict__ b1,
    const float*  __restrict__ w2,
    const float*  __restrict__ b2,
    float*        __restrict__ out)
{
    __shared__ float Wsh[ENC * ROWP];      // 9600 B
    __shared__ float b1sh[EDIM], w2sh[EDIM];
    __shared__ float frsh[NFREQ];
    __shared__ int   list[MAXF];           // fragment indices for this gene slot
    __shared__ float svals[MAXF];          // per-fragment scalar contributions
    __shared__ int   cntarr[256];
    __shared__ int   starts[256];

    const int g = blockIdx.x;              // gene slot in minibatch
    const int t = threadIdx.x;
    const int gene = genes_oi[g];

    // Stage per-gene parameters
    const float* Wg = W1 + (size_t)gene * (ENC * EDIM);
    for (int i = t; i < ENC * EDIM; i += 256) {
        int e = i / EDIM, o = i - e * EDIM;
        Wsh[e * ROWP + o] = Wg[i];
    }
    if (t < EDIM)  { b1sh[t] = b1[gene * EDIM + t]; w2sh[t] = w2[gene * EDIM + t]; }
    if (t < NFREQ) { frsh[t] = g_freqs[t]; }

    // Per-cell segment range for this gene slot (thread t <-> cell t)
    int a = 0, b = 0;
    if (t < NCELLS) {
        int s = t * NGENES_MB + g;
        a = g_seg_start[s];
        b = g_seg_start[s + 1];
    }
    int mycnt = b - a;
    cntarr[t] = mycnt;
    __syncthreads();

    // Inclusive Hillis-Steele scan (256 entries) -> deterministic placement
    for (int off = 1; off < 256; off <<= 1) {
        int v = cntarr[t];
        int add = (t >= off) ? cntarr[t - off] : 0;
        __syncthreads();
        cntarr[t] = v + add;
        __syncthreads();
    }
    int total = cntarr[255];
    int mystart = cntarr[t] - mycnt;
    starts[t] = mystart;
    for (int i = 0; i < mycnt; i++) {
        int pos = mystart + i;
        if (pos < MAXF) list[pos] = a + i;
    }
    __syncthreads();
    if (total > MAXF) total = MAXF;  // statistically unreachable guard

    // Per-gene params into registers (identical across threads)
    float b1r[EDIM], w2r[EDIM];
    #pragma unroll
    for (int o = 0; o < EDIM; o++) { b1r[o] = b1sh[o]; w2r[o] = w2sh[o]; }

    // Main per-fragment compute
    for (int idx = t; idx < total; idx += 256) {
        const int f = list[idx];
        const float2 xy = coords[f];

        float h[EDIM];
        #pragma unroll
        for (int o = 0; o < EDIM; o++) h[o] = b1r[o];

        #pragma unroll 2
        for (int j = 0; j < NFREQ; j++) {
            const float fq = frsh[j];
            float s0, c0, s1, c1;
            sincos_fast(xy.x * fq, s0, c0);
            sincos_fast(xy.y * fq, s1, c1);
            // enc rows: 2j (sin x0), 2j+1 (cos x0), 100+2j (sin x1), 101+2j (cos x1)
            const float* w0 = &Wsh[(2 * j) * ROWP];
            const float* w1p = &Wsh[(100 + 2 * j) * ROWP];
            #pragma unroll
            for (int o = 0; o < EDIM; o++) {
                float acc = h[o];
                acc = fmaf(s0, w0[o],        acc);
                acc = fmaf(c0, w0[ROWP + o], acc);
                acc = fmaf(s1, w1p[o],       acc);
                acc = fmaf(c1, w1p[ROWP + o], acc);
                h[o] = acc;
            }
        }

        // sigmoid + per-gene readout weights
        float s = 0.0f;
        #pragma unroll
        for (int o = 0; o < EDIM; o++) {
            float sig = __fdividef(1.0f, 1.0f + __expf(-h[o]));
            s = fmaf(w2r[o], sig, s);
        }
        svals[idx] = s;
    }
    __syncthreads();

    // Deterministic per-cell reduction (fragments of cell t are contiguous)
    if (t < NCELLS) {
        float acc = b2[gene];
        int st = starts[t];
        for (int i = 0; i < mycnt; i++) {
            int pos = st + i;
            if (pos < MAXF) acc += svals[pos];
        }
        out[t * NGENES_MB + g] = acc;
    }
}

// ---------------------------------------------------------------------------
// Launch
// Inputs (metadata order): 0 coordinates[F,2] f32, 1 genemapping i32 (unused),
// 2 local_cellxgene_ix i32, 3 genes_oi i32, 4 W1[2000,200,10] f32,
// 5 b1[2000,10] f32, 6 w2[2000,10] f32, 7 b2[2000] f32, (8,9 scalars)
// ---------------------------------------------------------------------------
extern "C" void kernel_launch(void* const* d_in, const int* in_sizes, int n_in,
                              void* d_out, int out_size) {
    const float2* coords   = (const float2*)d_in[0];
    const int*    ix       = (const int*)d_in[2];
    const int*    genes_oi = (const int*)d_in[3];
    const float*  W1       = (const float*)d_in[4];
    const float*  b1       = (const float*)d_in[5];
    const float*  w2       = (const float*)d_in[6];
    const float*  b2       = (const float*)d_in[7];
    float*        out      = (float*)d_out;

    init_freqs_kernel<<<1, 64>>>();
    seg_bounds_kernel<<<(NSEG + 1 + 255) / 256, 256>>>(ix);
    frag_gene_kernel<<<NGENES_MB, 256>>>(coords, genes_oi, W1, b1, w2, b2, out);
}

// round 2
// speedup vs baseline: 1.3969x; 1.3969x over previous
#include <cuda_runtime.h>
#include <math.h>

// Problem constants (fixed by the reference setup)
#define NFRAG     131072
#define NCELLS    200
#define NGENES_MB 500
#define NSEG      (NCELLS * NGENES_MB)   // 100000
#define NFREQ     50
#define ENC       200                    // 4 * NFREQ
#define EDIM      10
#define ROWP      12                     // padded row stride (floats): 48B, 16B-aligned rows
#define MAXF      512                    // max fragments per gene slot (mean ~262, sd ~16)

typedef unsigned long long u64;

// Scratch (no cudaMalloc allowed)
__device__ int   g_seg_start[NSEG + 1];
__device__ float g_freqs[NFREQ];

// ---------------------------------------------------------------------------
// f32x2 packed helpers (sm_103a FMA pipe, 2 FLOPs/instr)
// ---------------------------------------------------------------------------
__device__ __forceinline__ u64 pk2(float a, float b) {
    u64 d; asm("mov.b64 %0,{%1,%2};" : "=l"(d) : "f"(a), "f"(b)); return d;
}
__device__ __forceinline__ u64 bc2(float a) {
    u64 d; asm("mov.b64 %0,{%1,%1};" : "=l"(d) : "f"(a)); return d;
}
__device__ __forceinline__ u64 fma2(u64 a, u64 b, u64 c) {
    u64 d; asm("fma.rn.f32x2 %0,%1,%2,%3;" : "=l"(d) : "l"(a), "l"(b), "l"(c)); return d;
}
__device__ __forceinline__ u64 mul2(u64 a, u64 b) {
    u64 d; asm("mul.rn.f32x2 %0,%1,%2;" : "=l"(d) : "l"(a), "l"(b)); return d;
}
__device__ __forceinline__ u64 add2(u64 a, u64 b) {
    u64 d; asm("add.rn.f32x2 %0,%1,%2;" : "=l"(d) : "l"(a), "l"(b)); return d;
}
__device__ __forceinline__ float lo2(u64 a) { return __uint_as_float((unsigned)a); }
__device__ __forceinline__ float hi2(u64 a) { return __uint_as_float((unsigned)(a >> 32)); }

// Quadrant fixup (bit-exact match of the scalar reference sincos)
__device__ __forceinline__ float quad_s(unsigned k, float sr, float cr) {
    unsigned b = (k & 1u) ? __float_as_uint(cr) : __float_as_uint(sr);
    return __uint_as_float(b ^ ((k & 2u) << 30));
}
__device__ __forceinline__ float quad_c(unsigned k, float sr, float cr) {
    unsigned b = (k & 1u) ? __float_as_uint(sr) : __float_as_uint(cr);
    return __uint_as_float(b ^ (((k + 1u) & 2u) << 30));
}

// ---------------------------------------------------------------------------
// Kernel 1: segment boundaries by neighbor-diff scatter over sorted index,
// plus exact f32 frequencies (double pow, matches jnp within ~1 ulp) on the
// first 50 threads. One launch replaces the old init + binary-search pair.
// ---------------------------------------------------------------------------
__global__ void seg_scatter_kernel(const int* __restrict__ ix) {
    int f = blockIdx.x * blockDim.x + threadIdx.x;
    if (f < NFREQ) {
        double e = (2.0 * (double)(f + 1)) / (double)NFREQ;
        g_freqs[f] = (float)(1.0 / pow(1000.0, e));
    }
    if (f >= NFRAG) return;
    int cur  = ix[f];
    int prev = (f == 0) ? -1 : ix[f - 1];
    for (int s = prev + 1; s <= cur; ++s) g_seg_start[s] = f;
    if (f == NFRAG - 1)
        for (int s = cur + 1; s <= NSEG; ++s) g_seg_start[s] = NFRAG;
}

// ---------------------------------------------------------------------------
// Kernel 2: one block per gene slot g.
//   - stage W1[genes_oi[g]] (200x10 padded to 200x12) in SMEM
//   - gather slot fragments (segments g, g+500, ...) via deterministic scan
//   - per fragment: packed f32x2 sincos encode + vectorized 200x10 dot
//     (LDS.128 + fma.rn.f32x2) + sigmoid + w2 reduce
//   - per-cell ordered reduction -> out[c, g]  (no atomics, deterministic)
// ---------------------------------------------------------------------------
__global__ __launch_bounds__(256, 2) void frag_gene_kernel(
    const float2* __restrict__ coords,
    const int*    __restrict__ genes_oi,
    const float*  __restrict__ W1,
    const float*  __restrict__ b1,
    const float*  __restrict__ w2,
    const float*  __restrict__ b2,
    float*        __restrict__ out)
{
    __shared__ __align__(16) float Wsh[ENC * ROWP];   // 9600 B, rows 48B apart
    __shared__ __align__(16) float b1sh[12], w2sh[12];
    __shared__ float frsh[NFREQ];
    __shared__ int   list[MAXF];
    __shared__ float svals[MAXF];
    __shared__ int   cntarr[256];
    __shared__ int   starts[256];

    const int g = blockIdx.x;
    const int t = threadIdx.x;
    const int gene = genes_oi[g];

    // Stage per-gene parameters
    const float* Wg = W1 + (size_t)gene * (ENC * EDIM);
    for (int i = t; i < ENC * EDIM; i += 256) {
        int e = i / EDIM, o = i - e * EDIM;
        Wsh[e * ROWP + o] = Wg[i];
    }
    if (t < EDIM)  { b1sh[t] = b1[gene * EDIM + t]; w2sh[t] = w2[gene * EDIM + t]; }
    if (t < NFREQ) { frsh[t] = g_freqs[t]; }

    // Per-cell segment range (thread t <-> cell t)
    int a = 0, b = 0;
    if (t < NCELLS) {
        int s = t * NGENES_MB + g;
        a = g_seg_start[s];
        b = g_seg_start[s + 1];
    }
    int mycnt = b - a;
    cntarr[t] = mycnt;
    __syncthreads();

    // Inclusive Hillis-Steele scan -> deterministic placement
    for (int off = 1; off < 256; off <<= 1) {
        int v = cntarr[t];
        int add = (t >= off) ? cntarr[t - off] : 0;
        __syncthreads();
        cntarr[t] = v + add;
        __syncthreads();
    }
    int total = cntarr[255];
    int mystart = cntarr[t] - mycnt;
    starts[t] = mystart;
    for (int i = 0; i < mycnt; i++) {
        int pos = mystart + i;
        if (pos < MAXF) list[pos] = a + i;
    }
    __syncthreads();
    if (total > MAXF) total = MAXF;   // statistically unreachable guard

    // Hoisted packed constants (CSE'd across the fragment loop)
    const u64 INV2   = bc2(0.63661977236758134f);        // 2/pi
    const u64 MAG2   = bc2(12582912.0f);                 // 1.5 * 2^23
    const u64 NMAG2  = bc2(-12582912.0f);
    const u64 NH2    = bc2(-1.57079637050628662109375f); // -pi/2 hi
    const u64 PLO2   = bc2(4.37113900018624283e-8f);     // pi/2 lo correction
    const u64 KS1    = bc2(-1.9515295891e-4f);
    const u64 KS2    = bc2(8.3321608736e-3f);
    const u64 KS3    = bc2(-1.6666654611e-1f);
    const u64 KC1    = bc2(2.443315711809948e-5f);
    const u64 KC2    = bc2(-1.388731625493765e-3f);
    const u64 KC3    = bc2(4.166664568298827e-2f);
    const u64 NHALF2 = bc2(-0.5f);
    const u64 ONE2v  = bc2(1.0f);

    // Per-gene params (uniform across threads)
    float w2r[EDIM];
    #pragma unroll
    for (int o = 0; o < EDIM; o++) w2r[o] = w2sh[o];
    const u64 B0 = pk2(b1sh[0], b1sh[1]);
    const u64 B1 = pk2(b1sh[2], b1sh[3]);
    const u64 B2 = pk2(b1sh[4], b1sh[5]);
    const u64 B3 = pk2(b1sh[6], b1sh[7]);
    const u64 B4 = pk2(b1sh[8], b1sh[9]);

    // Main per-fragment compute
    for (int idx = t; idx < total; idx += 256) {
        const int f = list[idx];
        const float2 xy = coords[f];
        const u64 xy2 = pk2(xy.x, xy.y);

        u64 h0 = B0, h1 = B1, h2a = B2, h3 = B3, h4 = B4;

        #pragma unroll 2
        for (int j = 0; j < NFREQ; j++) {
            const float fq = frsh[j];
            const u64 t2 = mul2(xy2, bc2(fq));

            // packed sincos (both coordinates at once)
            u64 qb = fma2(t2, INV2, MAG2);
            unsigned k0 = (unsigned)qb, k1 = (unsigned)(qb >> 32);
            u64 q  = add2(qb, NMAG2);
            u64 r  = fma2(q, NH2, t2);
            r      = fma2(q, PLO2, r);
            u64 s2 = mul2(r, r);
            u64 ps = fma2(s2, KS1, KS2);
            ps     = fma2(ps, s2, KS3);
            u64 sr = fma2(ps, mul2(s2, r), r);
            u64 pc = fma2(s2, KC1, KC2);
            pc     = fma2(pc, s2, KC3);
            pc     = fma2(pc, s2, NHALF2);
            u64 cr = fma2(pc, s2, ONE2v);
            float srl = lo2(sr), srh = hi2(sr), crl = lo2(cr), crh = hi2(cr);
            float s0 = quad_s(k0, srl, crl), c0 = quad_c(k0, srl, crl);
            float s1 = quad_s(k1, srh, crh), c1 = quad_c(k1, srh, crh);

            // 4 enc rows: 2j (sin x0), 2j+1 (cos x0), 100+2j (sin x1), 101+2j (cos x1)
            const float* r0 = &Wsh[(2 * j) * ROWP];
            {
                const u64 vv = bc2(s0);
                const ulonglong2* p = (const ulonglong2*)r0;
                ulonglong2 ab = p[0], cd = p[1];
                u64 e4 = ((const u64*)r0)[4];
                h0 = fma2(vv, ab.x, h0); h1 = fma2(vv, ab.y, h1);
                h2a = fma2(vv, cd.x, h2a); h3 = fma2(vv, cd.y, h3);
                h4 = fma2(vv, e4, h4);
            }
            {
                const float* rp = r0 + ROWP;
                const u64 vv = bc2(c0);
                const ulonglong2* p = (const ulonglong2*)rp;
                ulonglong2 ab = p[0], cd = p[1];
                u64 e4 = ((const u64*)rp)[4];
                h0 = fma2(vv, ab.x, h0); h1 = fma2(vv, ab.y, h1);
                h2a = fma2(vv, cd.x, h2a); h3 = fma2(vv, cd.y, h3);
                h4 = fma2(vv, e4, h4);
            }
            {
                const float* rp = r0 + 100 * ROWP;
                const u64 vv = bc2(s1);
                const ulonglong2* p = (const ulonglong2*)rp;
                ulonglong2 ab = p[0], cd = p[1];
                u64 e4 = ((const u64*)rp)[4];
                h0 = fma2(vv, ab.x, h0); h1 = fma2(vv, ab.y, h1);
                h2a = fma2(vv, cd.x, h2a); h3 = fma2(vv, cd.y, h3);
                h4 = fma2(vv, e4, h4);
            }
            {
                const float* rp = r0 + 101 * ROWP;
                const u64 vv = bc2(c1);
                const ulonglong2* p = (const ulonglong2*)rp;
                ulonglong2 ab = p[0], cd = p[1];
                u64 e4 = ((const u64*)rp)[4];
                h0 = fma2(vv, ab.x, h0); h1 = fma2(vv, ab.y, h1);
                h2a = fma2(vv, cd.x, h2a); h3 = fma2(vv, cd.y, h3);
                h4 = fma2(vv, e4, h4);
            }
        }

        // sigmoid + per-gene readout weights
        float hv[EDIM] = { lo2(h0), hi2(h0), lo2(h1), hi2(h1), lo2(h2a),
                           hi2(h2a), lo2(h3), hi2(h3), lo2(h4), hi2(h4) };
        float s = 0.0f;
        #pragma unroll
        for (int o = 0; o < EDIM; o++) {
            float sig = __fdividef(1.0f, 1.0f + __expf(-hv[o]));
            s = fmaf(w2r[o], sig, s);
        }
        svals[idx] = s;
    }
    __syncthreads();

    // Deterministic per-cell reduction (cell t's fragments are contiguous)
    if (t < NCELLS) {
        float acc = b2[gene];
        int st = starts[t];
        for (int i = 0; i < mycnt; i++) {
            int pos = st + i;
            if (pos < MAXF) acc += svals[pos];
        }
        out[t * NGENES_MB + g] = acc;
    }
}

// ---------------------------------------------------------------------------
// Launch
// Inputs (metadata order): 0 coordinates[F,2] f32, 1 genemapping i32 (unused),
// 2 local_cellxgene_ix i32, 3 genes_oi i32, 4 W1[2000,200,10] f32,
// 5 b1[2000,10] f32, 6 w2[2000,10] f32, 7 b2[2000] f32, (8,9 scalars)
// ---------------------------------------------------------------------------
extern "C" void kernel_launch(void* const* d_in, const int* in_sizes, int n_in,
                              void* d_out, int out_size) {
    const float2* coords   = (const float2*)d_in[0];
    const int*    ix       = (const int*)d_in[2];
    const int*    genes_oi = (const int*)d_in[3];
    const float*  W1       = (const float*)d_in[4];
    const float*  b1       = (const float*)d_in[5];
    const float*  w2       = (const float*)d_in[6];
    const float*  b2       = (const float*)d_in[7];
    float*        out      = (float*)d_out;

    seg_scatter_kernel<<<(NFRAG + 255) / 256, 256>>>(ix);
    frag_gene_kernel<<<NGENES_MB, 256>>>(coords, genes_oi, W1, b1, w2, b2, out);
}